// round 8
// baseline (speedup 1.0000x reference)
#include <cuda_runtime.h>
#include <cstdint>

#define B_ 4
#define S_ 2048
#define E_ 1024
#define H_ 128
#define M_ (B_*S_)

#define SCALE_ 11.31370849898476f   // sqrt(128)

#define NSPLIT 4
#define KT 32
#define QTB 64           // q rows per block
#define NQT (S_/QTB)     // 32 q-tiles per batch

// Scratch (device globals: no allocation allowed)
__device__ float g_q[M_*H_];
__device__ float g_k[M_*H_];
__device__ float g_v[M_*H_];
__device__ float g_opart[(size_t)NSPLIT*M_*H_];
__device__ float g_mpart[NSPLIT*M_];
__device__ float g_lpart[NSPLIT*M_];

// ---------------------------------------------------------------------------
// tf32 helpers
// ---------------------------------------------------------------------------
__device__ __forceinline__ unsigned f2tf(float x) {
    unsigned r;
    asm("cvt.rna.tf32.f32 %0, %1;" : "=r"(r) : "f"(x));
    return r;
}
__device__ __forceinline__ void split_tf(float x, unsigned& hi, unsigned& lo) {
    hi = f2tf(x);
    lo = f2tf(x - __uint_as_float(hi));
}

#define MMA_TF32(d, a, b) \
    asm volatile("mma.sync.aligned.m16n8k8.row.col.f32.tf32.tf32.f32 " \
        "{%0,%1,%2,%3}, {%4,%5,%6,%7}, {%8,%9}, {%0,%1,%2,%3};" \
        : "+f"((d)[0]), "+f"((d)[1]), "+f"((d)[2]), "+f"((d)[3]) \
        : "r"((a)[0]), "r"((a)[1]), "r"((a)[2]), "r"((a)[3]), \
          "r"((b)[0]), "r"((b)[1]))

// ---------------------------------------------------------------------------
// Projection GEMM via tf32x3 mma with PAIRED PRE-SPLIT smem planes:
// out[m][h] = sum_e x[m][e]*W[h][e].  BM=128, BN=128(=H), BK=16.
// 256 threads = 8 warps (4m x 2n), warp tile 32x64.
// Each smem value is a float2 (tf32-hi, tf32-lo), split ONCE at load time.
// Mainloop fragment loads are single LDS.64 (hi+lo together), zero cvt.
// Plane: [128 rows][16 k-slots] float2; slot = k ^ (((row&3)<<2)|((row&4)>>2)).
// All fragment rows are ≡ g (mod 8) so the swizzle is a per-thread constant.
// smem = 2 planes * 16KB = 32KB static.
// ---------------------------------------------------------------------------
__global__ __launch_bounds__(256, 2) void proj_kernel(
    const float* __restrict__ x,
    const float* __restrict__ Wq,
    const float* __restrict__ Wk,
    const float* __restrict__ Wv)
{
    const float* W;
    float* out;
    float oscale;
    if (blockIdx.y == 0)      { W = Wq; out = g_q; oscale = SCALE_; }
    else if (blockIdx.y == 1) { W = Wk; out = g_k; oscale = 1.0f; }
    else                      { W = Wv; out = g_v; oscale = 1.0f; }

    __shared__ float XsP[128 * 32];   // 16KB: 128 rows x 16 float2 slots
    __shared__ float WsP[128 * 32];   // 16KB

    const int tid  = threadIdx.x;
    const int w    = tid >> 5;
    const int lane = tid & 31;
    const int g    = lane >> 2;
    const int tig  = lane & 3;

    const int m0 = blockIdx.x * 128;
    const int mw = (w >> 1) * 32;    // warp m-base
    const int nw = (w & 1) * 64;     // warp n-base

    // ---- load/split/store slots: 2 float4 of X + 2 of W per thread ----
    const int f4a  = tid;                  // 0..255
    const int f4b  = tid + 256;            // 256..511
    const int rowa = f4a >> 2, c4a = f4a & 3;
    const int rowb = f4b >> 2, c4b = f4b & 3;
    // swizzle per row: swz7 = ((row&3)<<2) | ((row&4)>>2)
    const int swa  = ((rowa & 3) << 2) | ((rowa & 4) >> 2);
    const int swb  = ((rowb & 3) << 2) | ((rowb & 4) >> 2);
    const int basea = rowa * 32 + (((c4a * 4) ^ (swa & 12)) << 1);  // float idx
    const int baseb = rowb * 32 + (((c4b * 4) ^ (swb & 12)) << 1);
    const int b0a  = swa & 1;    // within-group permutation bit
    const int b0b  = swb & 1;
    const float* xsrca = &x[(size_t)(m0 + rowa) * E_ + c4a * 4];
    const float* xsrcb = &x[(size_t)(m0 + rowb) * E_ + c4b * 4];
    const float* wsrca = &W[(size_t)rowa * E_ + c4a * 4];
    const float* wsrcb = &W[(size_t)rowb * E_ + c4b * 4];

    float acc[2][8][4];
#pragma unroll
    for (int i = 0; i < 2; i++)
#pragma unroll
        for (int j = 0; j < 8; j++)
#pragma unroll
            for (int c = 0; c < 4; c++) acc[i][j][c] = 0.0f;

    // ---- fragment read constants ----
    const int swzT = ((g & 3) << 2) | ((g & 4) >> 2);    // per-thread row swizzle
    const int s00  = (tig ^ swzT) << 1;                  // float idx of slot k=tig
    const float* xA = &XsP[(mw + g) * 32];
    const float* wB = &WsP[(nw + g) * 32];

    // prologue: stage tile 0
    float4 xa = *(const float4*)xsrca;
    float4 xb = *(const float4*)xsrcb;
    float4 wa = *(const float4*)wsrca;
    float4 wb = *(const float4*)wsrcb;

    for (int t = 0; t < E_ / 16; t++) {
        // ---- split + store staged tile ----
        {
            float2 p[4];
            float h;
#define SPLITV(val, slot) \
            h = __uint_as_float(f2tf(val)); \
            p[slot] = make_float2(h, __uint_as_float(f2tf((val) - h)))
#define STORE4(plane, base, b0v, v4) \
            SPLITV((v4).x, 0 ^ (b0v)); SPLITV((v4).y, 1 ^ (b0v)); \
            SPLITV((v4).z, 2 ^ (b0v)); SPLITV((v4).w, 3 ^ (b0v)); \
            *(float4*)&plane[base]     = make_float4(p[0].x, p[0].y, p[1].x, p[1].y); \
            *(float4*)&plane[base + 4] = make_float4(p[2].x, p[2].y, p[3].x, p[3].y)
            STORE4(XsP, basea, b0a, xa);
            STORE4(XsP, baseb, b0b, xb);
            STORE4(WsP, basea, b0a, wa);
            STORE4(WsP, baseb, b0b, wb);
#undef STORE4
#undef SPLITV
        }
        __syncthreads();

        // ---- prefetch next tile into registers (hidden under compute) ----
        if (t + 1 < E_ / 16) {
            const int ko = (t + 1) * 16;
            xa = *(const float4*)(xsrca + ko);
            xb = *(const float4*)(xsrcb + ko);
            wa = *(const float4*)(wsrca + ko);
            wb = *(const float4*)(wsrcb + ko);
        }

        // ---- compute: 2 k8-chunks, all loads are LDS.64 of (hi,lo) ----
#pragma unroll
        for (int kk = 0; kk < 2; kk++) {
            const int sk0 = s00 ^ (kk << 4);   // slot k=8kk+tig   (float idx)
            const int sk1 = sk0 ^ 8;           // slot k=8kk+tig+4

            unsigned aH[2][4], aL[2][4];
#pragma unroll
            for (int i = 0; i < 2; i++) {
                const float* xr = xA + i * 512;            // rows mw+16i+g
                float2 v00 = *(const float2*)(xr + sk0);
                float2 v10 = *(const float2*)(xr + 256 + sk0);   // row +8
                float2 v01 = *(const float2*)(xr + sk1);
                float2 v11 = *(const float2*)(xr + 256 + sk1);
                aH[i][0] = __float_as_uint(v00.x); aL[i][0] = __float_as_uint(v00.y);
                aH[i][1] = __float_as_uint(v10.x); aL[i][1] = __float_as_uint(v10.y);
                aH[i][2] = __float_as_uint(v01.x); aL[i][2] = __float_as_uint(v01.y);
                aH[i][3] = __float_as_uint(v11.x); aL[i][3] = __float_as_uint(v11.y);
            }
#pragma unroll
            for (int j = 0; j < 8; j++) {
                const float* wr = wB + j * 256;            // rows nw+8j+g
                float2 bv0 = *(const float2*)(wr + sk0);
                float2 bv1 = *(const float2*)(wr + sk1);
                unsigned bH[2], bL[2];
                bH[0] = __float_as_uint(bv0.x); bL[0] = __float_as_uint(bv0.y);
                bH[1] = __float_as_uint(bv1.x); bL[1] = __float_as_uint(bv1.y);
#pragma unroll
                for (int i = 0; i < 2; i++) {
                    MMA_TF32(acc[i][j], aH[i], bH);
                    MMA_TF32(acc[i][j], aH[i], bL);
                    MMA_TF32(acc[i][j], aL[i], bH);
                }
            }
        }
        __syncthreads();
    }

    // --- epilogue: C rows m0+mw+16i+{g, g+8}, cols nw+8j+2tig(+1) ---
#pragma unroll
    for (int i = 0; i < 2; i++) {
        const size_t r0 = (size_t)(m0 + mw + 16 * i + g);
#pragma unroll
        for (int j = 0; j < 8; j++) {
            const int col = nw + 8 * j + 2 * tig;
            *(float2*)&out[r0 * H_ + col] =
                make_float2(acc[i][j][0] * oscale, acc[i][j][1] * oscale);
            *(float2*)&out[(r0 + 8) * H_ + col] =
                make_float2(acc[i][j][2] * oscale, acc[i][j][3] * oscale);
        }
    }
}

// ---------------------------------------------------------------------------
// Flash attention: tf32x3 mma.sync. 128 threads (4 warps), QTB=64, KT=32,
// NSPLIT=4 k-split. Static smem = 49152 B exactly. (unchanged, passing)
// ---------------------------------------------------------------------------
__global__ __launch_bounds__(128, 4) void attn_kernel()
{
    __shared__ float Qs[QTB * 128];   // 32KB
    __shared__ float KVs[KT * 128];   // 16KB (K phase, then V phase)

    const int tid  = threadIdx.x;
    const int w    = tid >> 5;
    const int lane = tid & 31;
    const int g    = lane >> 2;
    const int tig  = lane & 3;

    const int bx   = blockIdx.x;
    const int wave = bx / 148;
    const int pos  = bx - wave * 148;
    int r;
    if      (wave == 1) r = 295 - pos;
    else if (wave == 3) r = 511 - pos;
    else                r = bx;

    const int qt    = (NQT - 1) - (r >> 4);
    const int sub   = r & 15;
    const int b     = sub & 3;
    const int split = sub >> 2;

    const int nkt = 2 * (qt + 1);
    const int ck  = (nkt + NSPLIT - 1) / NSPLIT;
    const int ks0 = split * ck;
    const int ks1 = min(ks0 + ck, nkt);
    if (ks0 >= ks1) return;

    const int    qb   = qt * QTB;
    const size_t base = (size_t)b * S_;

#pragma unroll
    for (int i = 0; i < 16; i++) {
        int f4 = tid + 128 * i;
        int row = f4 >> 5, c4 = f4 & 31;
        *(float4*)&Qs[row * 128 + ((c4 ^ (row & 7)) << 2)] =
            *(const float4*)&g_q[(base + qb + row) * H_ + c4 * 4];
    }

    float acc[16][4];
#pragma unroll
    for (int nt = 0; nt < 16; nt++)
#pragma unroll
        for (int j = 0; j < 4; j++) acc[nt][j] = 0.0f;

    float mA = -1e30f, mB = -1e30f, lA = 0.0f, lB = 0.0f;
    const int rA   = 16 * w + g;
    const int rowA = qb + rA;
    const int rowB = rowA + 8;

    const float* qrowA = &Qs[rA * 128 + tig];
    const float* qrowB = qrowA + 8 * 128;

    for (int kt = ks0; kt < ks1; kt++) {
        const int kb = kt * KT;

        __syncthreads();
#pragma unroll
        for (int i = 0; i < 8; i++) {
            int f4 = tid + 128 * i;
            int row = f4 >> 5, c4 = f4 & 31;
            *(float4*)&KVs[row * 128 + ((c4 ^ (row & 7)) << 2)] =
                *(const float4*)&g_k[(base + kb + row) * H_ + c4 * 4];
        }
        __syncthreads();

        float s[4][4];
#pragma unroll
        for (int nt = 0; nt < 4; nt++)
#pragma unroll
            for (int j = 0; j < 4; j++) s[nt][j] = 0.0f;

#pragma unroll
        for (int ks = 0; ks < 16; ks++) {
            const int c0 = ((2 * ks)     ^ g) << 2;
            const int c1 = ((2 * ks + 1) ^ g) << 2;
            unsigned aH[4], aL[4];
            split_tf(qrowA[c0], aH[0], aL[0]);
            split_tf(qrowB[c0], aH[1], aL[1]);
            split_tf(qrowA[c1], aH[2], aL[2]);
            split_tf(qrowB[c1], aH[3], aL[3]);
#pragma unroll
            for (int nt = 0; nt < 4; nt++) {
                const float* kr = &KVs[(8 * nt + g) * 128 + tig];
                unsigned bH[2], bL[2];
                split_tf(kr[c0], bH[0], bL[0]);
                split_tf(kr[c1], bH[1], bL[1]);
                MMA_TF32(s[nt], aH, bH);
                MMA_TF32(s[nt], aH, bL);
                MMA_TF32(s[nt], aL, bH);
            }
        }

#pragma unroll
        for (int nt = 0; nt < 4; nt++) {
            int c0 = kb + 8 * nt + 2 * tig;
            int c1 = c0 + 1;
            if (c0 > rowA) s[nt][0] = -1e30f;
            if (c1 > rowA) s[nt][1] = -1e30f;
            if (c0 > rowB) s[nt][2] = -1e30f;
            if (c1 > rowB) s[nt][3] = -1e30f;
        }

        float mxA = -1e30f, mxB = -1e30f;
#pragma unroll
        for (int nt = 0; nt < 4; nt++) {
            mxA = fmaxf(mxA, fmaxf(s[nt][0], s[nt][1]));
            mxB = fmaxf(mxB, fmaxf(s[nt][2], s[nt][3]));
        }
        mxA = fmaxf(mxA, __shfl_xor_sync(0xffffffffu, mxA, 1));
        mxA = fmaxf(mxA, __shfl_xor_sync(0xffffffffu, mxA, 2));
        mxB = fmaxf(mxB, __shfl_xor_sync(0xffffffffu, mxB, 1));
        mxB = fmaxf(mxB, __shfl_xor_sync(0xffffffffu, mxB, 2));

        float mAn = fmaxf(mA, mxA), mBn = fmaxf(mB, mxB);
        float cA = __expf(mA - mAn), cB = __expf(mB - mBn);
        float sumA = 0.0f, sumB = 0.0f;
#pragma unroll
        for (int nt = 0; nt < 4; nt++) {
            s[nt][0] = __expf(s[nt][0] - mAn);
            s[nt][1] = __expf(s[nt][1] - mAn);
            s[nt][2] = __expf(s[nt][2] - mBn);
            s[nt][3] = __expf(s[nt][3] - mBn);
            sumA += s[nt][0] + s[nt][1];
            sumB += s[nt][2] + s[nt][3];
        }
        sumA += __shfl_xor_sync(0xffffffffu, sumA, 1);
        sumA += __shfl_xor_sync(0xffffffffu, sumA, 2);
        sumB += __shfl_xor_sync(0xffffffffu, sumB, 1);
        sumB += __shfl_xor_sync(0xffffffffu, sumB, 2);
        lA = lA * cA + sumA;
        lB = lB * cB + sumB;
        mA = mAn; mB = mBn;
#pragma unroll
        for (int nt = 0; nt < 16; nt++) {
            acc[nt][0] *= cA; acc[nt][1] *= cA;
            acc[nt][2] *= cB; acc[nt][3] *= cB;
        }

        __syncthreads();
#pragma unroll
        for (int i = 0; i < 8; i++) {
            int f4 = tid + 128 * i;
            int row = f4 >> 5, c4 = f4 & 31;
            *(float4*)&KVs[row * 128 + ((c4 ^ (row & 7)) << 2)] =
                *(const float4*)&g_v[(base + kb + row) * H_ + c4 * 4];
        }
        __syncthreads();

        const int srcE = (lane & ~3) | (tig >> 1);
        const int srcO = srcE + 2;
        const int gh   = g >> 2;
        const int gl   = g & 3;
#pragma unroll
        for (int ka = 0; ka < 4; ka++) {
            float e, o, a0f, a1f, a2f, a3f;
            e = __shfl_sync(0xffffffffu, s[ka][0], srcE);
            o = __shfl_sync(0xffffffffu, s[ka][1], srcE);
            a0f = (tig & 1) ? o : e;
            e = __shfl_sync(0xffffffffu, s[ka][0], srcO);
            o = __shfl_sync(0xffffffffu, s[ka][1], srcO);
            a2f = (tig & 1) ? o : e;
            e = __shfl_sync(0xffffffffu, s[ka][2], srcE);
            o = __shfl_sync(0xffffffffu, s[ka][3], srcE);
            a1f = (tig & 1) ? o : e;
            e = __shfl_sync(0xffffffffu, s[ka][2], srcO);
            o = __shfl_sync(0xffffffffu, s[ka][3], srcO);
            a3f = (tig & 1) ? o : e;

            unsigned aH[4], aL[4];
            split_tf(a0f, aH[0], aL[0]);
            split_tf(a1f, aH[1], aL[1]);
            split_tf(a2f, aH[2], aL[2]);
            split_tf(a3f, aH[3], aL[3]);

            const float* v0 = &KVs[(8 * ka + tig) * 128 + gl];
            const float* v1 = &KVs[(8 * ka + tig + 4) * 128 + gl];
#pragma unroll
            for (int nt = 0; nt < 16; nt++) {
                const int o0 = ((2 * nt + gh) ^ tig) << 2;
                const int o1 = o0 ^ 16;
                unsigned bH[2], bL[2];
                split_tf(v0[o0], bH[0], bL[0]);
                split_tf(v1[o1], bH[1], bL[1]);
                MMA_TF32(acc[nt], aH, bH);
                MMA_TF32(acc[nt], aH, bL);
                MMA_TF32(acc[nt], aL, bH);
            }
        }
    }

    const size_t growA = (size_t)split * M_ + base + rowA;
    const size_t growB = growA + 8;
#pragma unroll
    for (int nt = 0; nt < 16; nt++) {
        *(float2*)&g_opart[growA * H_ + 8 * nt + 2 * tig] =
            make_float2(acc[nt][0], acc[nt][1]);
        *(float2*)&g_opart[growB * H_ + 8 * nt + 2 * tig] =
            make_float2(acc[nt][2], acc[nt][3]);
    }
    if (tig == 0) {
        g_mpart[growA] = mA; g_lpart[growA] = lA;
        g_mpart[growB] = mB; g_lpart[growB] = lB;
    }
}

// ---------------------------------------------------------------------------
// Combine kernel: merge NSPLIT partials per row.
// ---------------------------------------------------------------------------
__global__ __launch_bounds__(256) void combine_kernel(float* __restrict__ out)
{
    const int t   = blockIdx.x * 256 + threadIdx.x;
    const int row = t >> 5;
    const int h   = (t & 31) * 4;

    const int qt  = (row & (S_ - 1)) >> 6;            // QTB=64
    const int nkt = 2 * (qt + 1);
    const int ck  = (nkt + NSPLIT - 1) / NSPLIT;

    float ms[NSPLIT];
    float M = -1e30f;
#pragma unroll
    for (int sp = 0; sp < NSPLIT; sp++) {
        bool valid = (sp * ck < nkt);
        ms[sp] = valid ? g_mpart[sp * M_ + row] : -1e30f;
        M = fmaxf(M, ms[sp]);
    }

    float L = 0.0f;
    float4 o = make_float4(0.f, 0.f, 0.f, 0.f);
#pragma unroll
    for (int sp = 0; sp < NSPLIT; sp++) {
        if (sp * ck < nkt) {
            float e = __expf(ms[sp] - M);
            L += e * g_lpart[sp * M_ + row];
            float4 v = *(const float4*)&g_opart[((size_t)sp * M_ + row) * H_ + h];
            o.x += e * v.x; o.y += e * v.y; o.z += e * v.z; o.w += e * v.w;
        }
    }
    float inv = 1.0f / L;
    float4 rr = make_float4(o.x * inv, o.y * inv, o.z * inv, o.w * inv);
    *(float4*)&out[(size_t)row * H_ + h] = rr;
}

// ---------------------------------------------------------------------------
extern "C" void kernel_launch(void* const* d_in, const int* in_sizes, int n_in,
                              void* d_out, int out_size)
{
    const float* x  = (const float*)d_in[0];
    const float* Wq = (const float*)d_in[1];
    const float* Wk = (const float*)d_in[2];
    const float* Wv = (const float*)d_in[3];
    float* out = (float*)d_out;

    dim3 pg(M_ / 128, 3);
    proj_kernel<<<pg, 256>>>(x, Wq, Wk, Wv);
    attn_kernel<<<NSPLIT * B_ * NQT, 128>>>();
    combine_kernel<<<(M_ * H_ / 4) / 256, 256>>>(out);
}

// round 10
// speedup vs baseline: 1.2740x; 1.2740x over previous
#include <cuda_runtime.h>
#include <cstdint>

#define B_ 4
#define S_ 2048
#define E_ 1024
#define H_ 128
#define M_ (B_*S_)

#define SCALE_ 11.31370849898476f   // sqrt(128)

#define NSPLIT 4
#define KT 32
#define QTB 64           // q rows per block
#define NQT (S_/QTB)     // 32 q-tiles per batch

// Scratch (device globals: no allocation allowed)
__device__ float g_q[M_*H_];
__device__ float g_k[M_*H_];
__device__ float g_v[M_*H_];
__device__ float g_opart[(size_t)NSPLIT*M_*H_];
__device__ float g_mpart[NSPLIT*M_];
__device__ float g_lpart[NSPLIT*M_];

// ---------------------------------------------------------------------------
// tf32 helpers
// ---------------------------------------------------------------------------
__device__ __forceinline__ unsigned f2tf(float x) {
    unsigned r;
    asm("cvt.rna.tf32.f32 %0, %1;" : "=r"(r) : "f"(x));
    return r;
}
__device__ __forceinline__ void split_tf(float x, unsigned& hi, unsigned& lo) {
    hi = f2tf(x);
    lo = f2tf(x - __uint_as_float(hi));
}

#define MMA_TF32(d, a, b) \
    asm volatile("mma.sync.aligned.m16n8k8.row.col.f32.tf32.tf32.f32 " \
        "{%0,%1,%2,%3}, {%4,%5,%6,%7}, {%8,%9}, {%0,%1,%2,%3};" \
        : "+f"((d)[0]), "+f"((d)[1]), "+f"((d)[2]), "+f"((d)[3]) \
        : "r"((a)[0]), "r"((a)[1]), "r"((a)[2]), "r"((a)[3]), \
          "r"((b)[0]), "r"((b)[1]))

#define CP_ASYNC16(dst, src) \
    asm volatile("cp.async.cg.shared.global [%0], [%1], 16;\n" \
        :: "r"(dst), "l"(src))
#define CP_COMMIT() asm volatile("cp.async.commit_group;\n" ::: "memory")
#define CP_WAIT(n)  asm volatile("cp.async.wait_group %0;\n" :: "n"(n) : "memory")

// ---------------------------------------------------------------------------
// Projection GEMM via tf32x3 mma: out[m][h] = sum_e x[m][e]*W[h][e]
// BM=64, BN=128(=H), BK=16, double-buffered cp.async pipeline.
// 256 threads = 8 warps (4m x 2n), warp tile 16x64, acc = 32 regs/thread.
// Grid (128,3) = 384 blocks; 3 CTAs/SM -> all co-resident, 24 warps/SM.
// smem = 2 * (64+128)*16*4 = 24KB static.
// Swizzle: float4 slot c4 of row r stored at c4 ^ ((r>>1)&3); for all
// fragment rows (≡ g mod 8) it folds to the per-thread constant (g>>1)&3.
// ---------------------------------------------------------------------------
__global__ __launch_bounds__(256, 3) void proj_kernel(
    const float* __restrict__ x,
    const float* __restrict__ Wq,
    const float* __restrict__ Wk,
    const float* __restrict__ Wv)
{
    const float* W;
    float* out;
    float oscale;
    if (blockIdx.y == 0)      { W = Wq; out = g_q; oscale = SCALE_; }
    else if (blockIdx.y == 1) { W = Wk; out = g_k; oscale = 1.0f; }
    else                      { W = Wv; out = g_v; oscale = 1.0f; }

    __shared__ float Xs[2][64 * 16];    // 4KB each
    __shared__ float Ws[2][128 * 16];   // 8KB each

    const int tid  = threadIdx.x;
    const int w    = tid >> 5;
    const int lane = tid & 31;
    const int g    = lane >> 2;
    const int tig  = lane & 3;

    const int m0 = blockIdx.x * 64;
    const int mw = (w >> 1) * 16;    // warp m-base
    const int nw = (w & 1) * 64;     // warp n-base

    // per-thread load slots: 1 float4 of X, 2 float4 of W
    const int rowx = tid >> 2, c4x = tid & 3;
    const int soffx = rowx * 16 + ((c4x ^ ((rowx >> 1) & 3)) << 2);
    const float* xsrc = &x[(size_t)(m0 + rowx) * E_ + c4x * 4];

    const int roww0 = tid >> 2, roww1 = roww0 + 64, c4w = tid & 3;
    const int soffw0 = roww0 * 16 + ((c4w ^ ((roww0 >> 1) & 3)) << 2);
    const int soffw1 = roww1 * 16 + ((c4w ^ ((roww1 >> 1) & 3)) << 2);
    const float* wsrc0 = &W[(size_t)roww0 * E_ + c4w * 4];
    const float* wsrc1 = &W[(size_t)roww1 * E_ + c4w * 4];

    unsigned xs_u32[2], ws_u32[2];
#pragma unroll
    for (int bb = 0; bb < 2; bb++) {
        xs_u32[bb] = (unsigned)__cvta_generic_to_shared(&Xs[bb][0]);
        ws_u32[bb] = (unsigned)__cvta_generic_to_shared(&Ws[bb][0]);
    }

    float acc[8][4];
#pragma unroll
    for (int j = 0; j < 8; j++)
#pragma unroll
        for (int c = 0; c < 4; c++) acc[j][c] = 0.0f;

    // fragment swizzle constant and column offsets
    const int sw = (g >> 1) & 3;
    const int o0k0 = ((0 ^ sw) << 2);   // kk=0: k=tig
    const int o1k0 = ((1 ^ sw) << 2);   //        k=tig+4
    const int o0k1 = ((2 ^ sw) << 2);   // kk=1
    const int o1k1 = ((3 ^ sw) << 2);

    const float* xfr[2];
    xfr[0] = &Xs[0][(mw + g) * 16 + tig];
    xfr[1] = &Xs[1][(mw + g) * 16 + tig];
    const float* wfr[2];
    wfr[0] = &Ws[0][(nw + g) * 16 + tig];
    wfr[1] = &Ws[1][(nw + g) * 16 + tig];

    // prologue: load tile 0 into buffer 0
    CP_ASYNC16(xs_u32[0] + soffx * 4, xsrc);
    CP_ASYNC16(ws_u32[0] + soffw0 * 4, wsrc0);
    CP_ASYNC16(ws_u32[0] + soffw1 * 4, wsrc1);
    CP_COMMIT();

    for (int t = 0; t < E_ / 16; t++) {
        const int buf = t & 1;
        if (t + 1 < E_ / 16) {
            const int nb = (t + 1) & 1;
            const int ko = (t + 1) * 16;
            CP_ASYNC16(xs_u32[nb] + soffx * 4, xsrc + ko);
            CP_ASYNC16(ws_u32[nb] + soffw0 * 4, wsrc0 + ko);
            CP_ASYNC16(ws_u32[nb] + soffw1 * 4, wsrc1 + ko);
            CP_COMMIT();
            CP_WAIT(1);
        } else {
            CP_WAIT(0);
        }
        __syncthreads();

#pragma unroll
        for (int kk = 0; kk < 2; kk++) {
            const int s0 = kk ? o0k1 : o0k0;
            const int s1 = kk ? o1k1 : o1k0;

            unsigned aH[4], aL[4];
            const float* xr = xfr[buf];                 // rows mw+g / mw+8+g
            split_tf(xr[s0],           aH[0], aL[0]);
            split_tf(xr[8 * 16 + s0],  aH[1], aL[1]);
            split_tf(xr[s1],           aH[2], aL[2]);
            split_tf(xr[8 * 16 + s1],  aH[3], aL[3]);

#pragma unroll
            for (int j = 0; j < 8; j++) {
                const float* wr = wfr[buf] + 8 * 16 * j;  // rows nw+8j+g
                unsigned bH[2], bL[2];
                split_tf(wr[s0], bH[0], bL[0]);
                split_tf(wr[s1], bH[1], bL[1]);
                MMA_TF32(acc[j], aH, bH);
                MMA_TF32(acc[j], aH, bL);
                MMA_TF32(acc[j], aL, bH);
            }
        }
        __syncthreads();
    }

    // --- epilogue: C rows m0+mw+{g, g+8}, cols nw+8j+2tig(+1) ---
    const size_t r0 = (size_t)(m0 + mw + g);
#pragma unroll
    for (int j = 0; j < 8; j++) {
        const int col = nw + 8 * j + 2 * tig;
        *(float2*)&out[r0 * H_ + col] =
            make_float2(acc[j][0] * oscale, acc[j][1] * oscale);
        *(float2*)&out[(r0 + 8) * H_ + col] =
            make_float2(acc[j][2] * oscale, acc[j][3] * oscale);
    }
}

// ---------------------------------------------------------------------------
// Flash attention: tf32x3 mma.sync. 128 threads (4 warps), QTB=64, KT=32,
// NSPLIT=4 k-split. Static smem = 49152 B exactly. (unchanged, passing)
// ---------------------------------------------------------------------------
__global__ __launch_bounds__(128, 4) void attn_kernel()
{
    __shared__ float Qs[QTB * 128];   // 32KB
    __shared__ float KVs[KT * 128];   // 16KB (K phase, then V phase)

    const int tid  = threadIdx.x;
    const int w    = tid >> 5;
    const int lane = tid & 31;
    const int g    = lane >> 2;
    const int tig  = lane & 3;

    const int bx   = blockIdx.x;
    const int wave = bx / 148;
    const int pos  = bx - wave * 148;
    int r;
    if      (wave == 1) r = 295 - pos;
    else if (wave == 3) r = 511 - pos;
    else                r = bx;

    const int qt    = (NQT - 1) - (r >> 4);
    const int sub   = r & 15;
    const int b     = sub & 3;
    const int split = sub >> 2;

    const int nkt = 2 * (qt + 1);
    const int ck  = (nkt + NSPLIT - 1) / NSPLIT;
    const int ks0 = split * ck;
    const int ks1 = min(ks0 + ck, nkt);
    if (ks0 >= ks1) return;

    const int    qb   = qt * QTB;
    const size_t base = (size_t)b * S_;

#pragma unroll
    for (int i = 0; i < 16; i++) {
        int f4 = tid + 128 * i;
        int row = f4 >> 5, c4 = f4 & 31;
        *(float4*)&Qs[row * 128 + ((c4 ^ (row & 7)) << 2)] =
            *(const float4*)&g_q[(base + qb + row) * H_ + c4 * 4];
    }

    float acc[16][4];
#pragma unroll
    for (int nt = 0; nt < 16; nt++)
#pragma unroll
        for (int j = 0; j < 4; j++) acc[nt][j] = 0.0f;

    float mA = -1e30f, mB = -1e30f, lA = 0.0f, lB = 0.0f;
    const int rA   = 16 * w + g;
    const int rowA = qb + rA;
    const int rowB = rowA + 8;

    const float* qrowA = &Qs[rA * 128 + tig];
    const float* qrowB = qrowA + 8 * 128;

    for (int kt = ks0; kt < ks1; kt++) {
        const int kb = kt * KT;

        __syncthreads();
#pragma unroll
        for (int i = 0; i < 8; i++) {
            int f4 = tid + 128 * i;
            int row = f4 >> 5, c4 = f4 & 31;
            *(float4*)&KVs[row * 128 + ((c4 ^ (row & 7)) << 2)] =
                *(const float4*)&g_k[(base + kb + row) * H_ + c4 * 4];
        }
        __syncthreads();

        float s[4][4];
#pragma unroll
        for (int nt = 0; nt < 4; nt++)
#pragma unroll
            for (int j = 0; j < 4; j++) s[nt][j] = 0.0f;

#pragma unroll
        for (int ks = 0; ks < 16; ks++) {
            const int c0 = ((2 * ks)     ^ g) << 2;
            const int c1 = ((2 * ks + 1) ^ g) << 2;
            unsigned aH[4], aL[4];
            split_tf(qrowA[c0], aH[0], aL[0]);
            split_tf(qrowB[c0], aH[1], aL[1]);
            split_tf(qrowA[c1], aH[2], aL[2]);
            split_tf(qrowB[c1], aH[3], aL[3]);
#pragma unroll
            for (int nt = 0; nt < 4; nt++) {
                const float* kr = &KVs[(8 * nt + g) * 128 + tig];
                unsigned bH[2], bL[2];
                split_tf(kr[c0], bH[0], bL[0]);
                split_tf(kr[c1], bH[1], bL[1]);
                MMA_TF32(s[nt], aH, bH);
                MMA_TF32(s[nt], aH, bL);
                MMA_TF32(s[nt], aL, bH);
            }
        }

#pragma unroll
        for (int nt = 0; nt < 4; nt++) {
            int c0 = kb + 8 * nt + 2 * tig;
            int c1 = c0 + 1;
            if (c0 > rowA) s[nt][0] = -1e30f;
            if (c1 > rowA) s[nt][1] = -1e30f;
            if (c0 > rowB) s[nt][2] = -1e30f;
            if (c1 > rowB) s[nt][3] = -1e30f;
        }

        float mxA = -1e30f, mxB = -1e30f;
#pragma unroll
        for (int nt = 0; nt < 4; nt++) {
            mxA = fmaxf(mxA, fmaxf(s[nt][0], s[nt][1]));
            mxB = fmaxf(mxB, fmaxf(s[nt][2], s[nt][3]));
        }
        mxA = fmaxf(mxA, __shfl_xor_sync(0xffffffffu, mxA, 1));
        mxA = fmaxf(mxA, __shfl_xor_sync(0xffffffffu, mxA, 2));
        mxB = fmaxf(mxB, __shfl_xor_sync(0xffffffffu, mxB, 1));
        mxB = fmaxf(mxB, __shfl_xor_sync(0xffffffffu, mxB, 2));

        float mAn = fmaxf(mA, mxA), mBn = fmaxf(mB, mxB);
        float cA = __expf(mA - mAn), cB = __expf(mB - mBn);
        float sumA = 0.0f, sumB = 0.0f;
#pragma unroll
        for (int nt = 0; nt < 4; nt++) {
            s[nt][0] = __expf(s[nt][0] - mAn);
            s[nt][1] = __expf(s[nt][1] - mAn);
            s[nt][2] = __expf(s[nt][2] - mBn);
            s[nt][3] = __expf(s[nt][3] - mBn);
            sumA += s[nt][0] + s[nt][1];
            sumB += s[nt][2] + s[nt][3];
        }
        sumA += __shfl_xor_sync(0xffffffffu, sumA, 1);
        sumA += __shfl_xor_sync(0xffffffffu, sumA, 2);
        sumB += __shfl_xor_sync(0xffffffffu, sumB, 1);
        sumB += __shfl_xor_sync(0xffffffffu, sumB, 2);
        lA = lA * cA + sumA;
        lB = lB * cB + sumB;
        mA = mAn; mB = mBn;
#pragma unroll
        for (int nt = 0; nt < 16; nt++) {
            acc[nt][0] *= cA; acc[nt][1] *= cA;
            acc[nt][2] *= cB; acc[nt][3] *= cB;
        }

        __syncthreads();
#pragma unroll
        for (int i = 0; i < 8; i++) {
            int f4 = tid + 128 * i;
            int row = f4 >> 5, c4 = f4 & 31;
            *(float4*)&KVs[row * 128 + ((c4 ^ (row & 7)) << 2)] =
                *(const float4*)&g_v[(base + kb + row) * H_ + c4 * 4];
        }
        __syncthreads();

        const int srcE = (lane & ~3) | (tig >> 1);
        const int srcO = srcE + 2;
        const int gh   = g >> 2;
        const int gl   = g & 3;
#pragma unroll
        for (int ka = 0; ka < 4; ka++) {
            float e, o, a0f, a1f, a2f, a3f;
            e = __shfl_sync(0xffffffffu, s[ka][0], srcE);
            o = __shfl_sync(0xffffffffu, s[ka][1], srcE);
            a0f = (tig & 1) ? o : e;
            e = __shfl_sync(0xffffffffu, s[ka][0], srcO);
            o = __shfl_sync(0xffffffffu, s[ka][1], srcO);
            a2f = (tig & 1) ? o : e;
            e = __shfl_sync(0xffffffffu, s[ka][2], srcE);
            o = __shfl_sync(0xffffffffu, s[ka][3], srcE);
            a1f = (tig & 1) ? o : e;
            e = __shfl_sync(0xffffffffu, s[ka][2], srcO);
            o = __shfl_sync(0xffffffffu, s[ka][3], srcO);
            a3f = (tig & 1) ? o : e;

            unsigned aH[4], aL[4];
            split_tf(a0f, aH[0], aL[0]);
            split_tf(a1f, aH[1], aL[1]);
            split_tf(a2f, aH[2], aL[2]);
            split_tf(a3f, aH[3], aL[3]);

            const float* v0 = &KVs[(8 * ka + tig) * 128 + gl];
            const float* v1 = &KVs[(8 * ka + tig + 4) * 128 + gl];
#pragma unroll
            for (int nt = 0; nt < 16; nt++) {
                const int o0 = ((2 * nt + gh) ^ tig) << 2;
                const int o1 = o0 ^ 16;
                unsigned bH[2], bL[2];
                split_tf(v0[o0], bH[0], bL[0]);
                split_tf(v1[o1], bH[1], bL[1]);
                MMA_TF32(acc[nt], aH, bH);
                MMA_TF32(acc[nt], aH, bL);
                MMA_TF32(acc[nt], aL, bH);
            }
        }
    }

    const size_t growA = (size_t)split * M_ + base + rowA;
    const size_t growB = growA + 8;
#pragma unroll
    for (int nt = 0; nt < 16; nt++) {
        *(float2*)&g_opart[growA * H_ + 8 * nt + 2 * tig] =
            make_float2(acc[nt][0], acc[nt][1]);
        *(float2*)&g_opart[growB * H_ + 8 * nt + 2 * tig] =
            make_float2(acc[nt][2], acc[nt][3]);
    }
    if (tig == 0) {
        g_mpart[growA] = mA; g_lpart[growA] = lA;
        g_mpart[growB] = mB; g_lpart[growB] = lB;
    }
}

// ---------------------------------------------------------------------------
// Combine kernel: merge NSPLIT partials per row.
// ---------------------------------------------------------------------------
__global__ __launch_bounds__(256) void combine_kernel(float* __restrict__ out)
{
    const int t   = blockIdx.x * 256 + threadIdx.x;
    const int row = t >> 5;
    const int h   = (t & 31) * 4;

    const int qt  = (row & (S_ - 1)) >> 6;            // QTB=64
    const int nkt = 2 * (qt + 1);
    const int ck  = (nkt + NSPLIT - 1) / NSPLIT;

    float ms[NSPLIT];
    float M = -1e30f;
#pragma unroll
    for (int sp = 0; sp < NSPLIT; sp++) {
        bool valid = (sp * ck < nkt);
        ms[sp] = valid ? g_mpart[sp * M_ + row] : -1e30f;
        M = fmaxf(M, ms[sp]);
    }

    float L = 0.0f;
    float4 o = make_float4(0.f, 0.f, 0.f, 0.f);
#pragma unroll
    for (int sp = 0; sp < NSPLIT; sp++) {
        if (sp * ck < nkt) {
            float e = __expf(ms[sp] - M);
            L += e * g_lpart[sp * M_ + row];
            float4 v = *(const float4*)&g_opart[((size_t)sp * M_ + row) * H_ + h];
            o.x += e * v.x; o.y += e * v.y; o.z += e * v.z; o.w += e * v.w;
        }
    }
    float inv = 1.0f / L;
    float4 rr = make_float4(o.x * inv, o.y * inv, o.z * inv, o.w * inv);
    *(float4*)&out[(size_t)row * H_ + h] = rr;
}

// ---------------------------------------------------------------------------
extern "C" void kernel_launch(void* const* d_in, const int* in_sizes, int n_in,
                              void* d_out, int out_size)
{
    const float* x  = (const float*)d_in[0];
    const float* Wq = (const float*)d_in[1];
    const float* Wk = (const float*)d_in[2];
    const float* Wv = (const float*)d_in[3];
    float* out = (float*)d_out;

    dim3 pg(M_ / 64, 3);
    proj_kernel<<<pg, 256>>>(x, Wq, Wk, Wv);
    attn_kernel<<<NSPLIT * B_ * NQT, 128>>>();
    combine_kernel<<<(M_ * H_ / 4) / 256, 256>>>(out);
}

// round 11
// speedup vs baseline: 1.4170x; 1.1123x over previous
#include <cuda_runtime.h>
#include <cstdint>

#define B_ 4
#define S_ 2048
#define E_ 1024
#define H_ 128
#define M_ (B_*S_)

#define SCALE_ 11.31370849898476f   // sqrt(128)

#define NSPLIT 4
#define KT 32
#define QTB 64           // q rows per block
#define NQT (S_/QTB)     // 32 q-tiles per batch

// Scratch (device globals: no allocation allowed)
__device__ float g_q[M_*H_];
__device__ float g_k[M_*H_];
__device__ float g_v[M_*H_];
__device__ float g_opart[(size_t)NSPLIT*M_*H_];
__device__ float g_mpart[NSPLIT*M_];
__device__ float g_lpart[NSPLIT*M_];

// ---------------------------------------------------------------------------
// tf32 helpers
// ---------------------------------------------------------------------------
__device__ __forceinline__ unsigned f2tf(float x) {
    unsigned r;
    asm("cvt.rna.tf32.f32 %0, %1;" : "=r"(r) : "f"(x));
    return r;
}
__device__ __forceinline__ void split_tf(float x, unsigned& hi, unsigned& lo) {
    hi = f2tf(x);
    lo = f2tf(x - __uint_as_float(hi));
}

#define MMA_TF32(d, a, b) \
    asm volatile("mma.sync.aligned.m16n8k8.row.col.f32.tf32.tf32.f32 " \
        "{%0,%1,%2,%3}, {%4,%5,%6,%7}, {%8,%9}, {%0,%1,%2,%3};" \
        : "+f"((d)[0]), "+f"((d)[1]), "+f"((d)[2]), "+f"((d)[3]) \
        : "r"((a)[0]), "r"((a)[1]), "r"((a)[2]), "r"((a)[3]), \
          "r"((b)[0]), "r"((b)[1]))

#define CP_ASYNC16(dst, src) \
    asm volatile("cp.async.cg.shared.global [%0], [%1], 16;\n" \
        :: "r"(dst), "l"(src))
#define CP_COMMIT() asm volatile("cp.async.commit_group;\n" ::: "memory")
#define CP_WAIT(n)  asm volatile("cp.async.wait_group %0;\n" :: "n"(n) : "memory")

// ---------------------------------------------------------------------------
// Projection GEMM via tf32x3 mma: out[m][h] = sum_e x[m][e]*W[h][e]
// BM=64, BN=128(=H), BK=16, double-buffered cp.async pipeline.
// 128 threads = 4 warps (2m x 2n), warp tile 32x64, acc = 64 regs/thread.
// Wide warp tile: each B-split pair feeds 6 mma (support/mma ~2.0 vs 4.6).
// Grid (128,3) = 384 blocks; 24KB smem -> >=3 CTAs/SM co-resident.
// Swizzle: float4 slot c4 of row r stored at c4 ^ ((r>>1)&3); for all
// fragment rows (≡ g mod 8) it folds to the per-thread constant (g>>1)&3.
// ---------------------------------------------------------------------------
__global__ __launch_bounds__(128, 4) void proj_kernel(
    const float* __restrict__ x,
    const float* __restrict__ Wq,
    const float* __restrict__ Wk,
    const float* __restrict__ Wv)
{
    const float* W;
    float* out;
    float oscale;
    if (blockIdx.y == 0)      { W = Wq; out = g_q; oscale = SCALE_; }
    else if (blockIdx.y == 1) { W = Wk; out = g_k; oscale = 1.0f; }
    else                      { W = Wv; out = g_v; oscale = 1.0f; }

    __shared__ float Xs[2][64 * 16];    // 4KB each
    __shared__ float Ws[2][128 * 16];   // 8KB each

    const int tid  = threadIdx.x;
    const int w    = tid >> 5;
    const int lane = tid & 31;
    const int g    = lane >> 2;
    const int tig  = lane & 3;

    const int m0 = blockIdx.x * 64;
    const int mw = (w >> 1) * 32;    // warp m-base (0 or 32)
    const int nw = (w & 1) * 64;     // warp n-base (0 or 64)

    // per-thread load slots: 2 float4 of X (rows r, r+32), 4 float4 of W
    const int rl  = tid >> 2, c4l = tid & 3;     // rows 0..31, slot 0..3
    int soffx[2], soffw[4];
    const float* xsrc[2];
    const float* wsrc[4];
#pragma unroll
    for (int i = 0; i < 2; i++) {
        int row = rl + 32 * i;
        soffx[i] = row * 16 + ((c4l ^ ((row >> 1) & 3)) << 2);
        xsrc[i]  = &x[(size_t)(m0 + row) * E_ + c4l * 4];
    }
#pragma unroll
    for (int i = 0; i < 4; i++) {
        int row = rl + 32 * i;
        soffw[i] = row * 16 + ((c4l ^ ((row >> 1) & 3)) << 2);
        wsrc[i]  = &W[(size_t)row * E_ + c4l * 4];
    }

    unsigned xs_u32[2], ws_u32[2];
#pragma unroll
    for (int bb = 0; bb < 2; bb++) {
        xs_u32[bb] = (unsigned)__cvta_generic_to_shared(&Xs[bb][0]);
        ws_u32[bb] = (unsigned)__cvta_generic_to_shared(&Ws[bb][0]);
    }

    float acc[2][8][4];
#pragma unroll
    for (int i = 0; i < 2; i++)
#pragma unroll
        for (int j = 0; j < 8; j++)
#pragma unroll
            for (int c = 0; c < 4; c++) acc[i][j][c] = 0.0f;

    // fragment swizzle constant and column offsets
    const int sw = (g >> 1) & 3;
    const int o0k0 = ((0 ^ sw) << 2);   // kk=0: k=tig
    const int o1k0 = ((1 ^ sw) << 2);   //        k=tig+4
    const int o0k1 = ((2 ^ sw) << 2);   // kk=1
    const int o1k1 = ((3 ^ sw) << 2);

    const float* xfr[2];
    xfr[0] = &Xs[0][(mw + g) * 16 + tig];
    xfr[1] = &Xs[1][(mw + g) * 16 + tig];
    const float* wfr[2];
    wfr[0] = &Ws[0][(nw + g) * 16 + tig];
    wfr[1] = &Ws[1][(nw + g) * 16 + tig];

    // prologue: load tile 0 into buffer 0
#pragma unroll
    for (int i = 0; i < 2; i++) CP_ASYNC16(xs_u32[0] + soffx[i] * 4, xsrc[i]);
#pragma unroll
    for (int i = 0; i < 4; i++) CP_ASYNC16(ws_u32[0] + soffw[i] * 4, wsrc[i]);
    CP_COMMIT();

    for (int t = 0; t < E_ / 16; t++) {
        const int buf = t & 1;
        if (t + 1 < E_ / 16) {
            const int nb = (t + 1) & 1;
            const int ko = (t + 1) * 16;
#pragma unroll
            for (int i = 0; i < 2; i++)
                CP_ASYNC16(xs_u32[nb] + soffx[i] * 4, xsrc[i] + ko);
#pragma unroll
            for (int i = 0; i < 4; i++)
                CP_ASYNC16(ws_u32[nb] + soffw[i] * 4, wsrc[i] + ko);
            CP_COMMIT();
            CP_WAIT(1);
        } else {
            CP_WAIT(0);
        }
        __syncthreads();

#pragma unroll
        for (int kk = 0; kk < 2; kk++) {
            const int s0 = kk ? o0k1 : o0k0;
            const int s1 = kk ? o1k1 : o1k0;

            unsigned aH[2][4], aL[2][4];
#pragma unroll
            for (int i = 0; i < 2; i++) {
                const float* xr = xfr[buf] + 16 * 16 * i;   // rows mw+16i+g
                split_tf(xr[s0],           aH[i][0], aL[i][0]);
                split_tf(xr[8 * 16 + s0],  aH[i][1], aL[i][1]);
                split_tf(xr[s1],           aH[i][2], aL[i][2]);
                split_tf(xr[8 * 16 + s1],  aH[i][3], aL[i][3]);
            }
#pragma unroll
            for (int j = 0; j < 8; j++) {
                const float* wr = wfr[buf] + 8 * 16 * j;    // rows nw+8j+g
                unsigned bH[2], bL[2];
                split_tf(wr[s0], bH[0], bL[0]);
                split_tf(wr[s1], bH[1], bL[1]);
#pragma unroll
                for (int i = 0; i < 2; i++) {
                    MMA_TF32(acc[i][j], aH[i], bH);
                    MMA_TF32(acc[i][j], aH[i], bL);
                    MMA_TF32(acc[i][j], aL[i], bH);
                }
            }
        }
        __syncthreads();
    }

    // --- epilogue: C rows m0+mw+16i+{g, g+8}, cols nw+8j+2tig(+1) ---
#pragma unroll
    for (int i = 0; i < 2; i++) {
        const size_t r0 = (size_t)(m0 + mw + 16 * i + g);
#pragma unroll
        for (int j = 0; j < 8; j++) {
            const int col = nw + 8 * j + 2 * tig;
            *(float2*)&out[r0 * H_ + col] =
                make_float2(acc[i][j][0] * oscale, acc[i][j][1] * oscale);
            *(float2*)&out[(r0 + 8) * H_ + col] =
                make_float2(acc[i][j][2] * oscale, acc[i][j][3] * oscale);
        }
    }
}

// ---------------------------------------------------------------------------
// Flash attention: tf32x3 mma.sync. 128 threads (4 warps), QTB=64, KT=32,
// NSPLIT=4 k-split. Static smem = 49152 B exactly. (unchanged, passing)
// ---------------------------------------------------------------------------
__global__ __launch_bounds__(128, 4) void attn_kernel()
{
    __shared__ float Qs[QTB * 128];   // 32KB
    __shared__ float KVs[KT * 128];   // 16KB (K phase, then V phase)

    const int tid  = threadIdx.x;
    const int w    = tid >> 5;
    const int lane = tid & 31;
    const int g    = lane >> 2;
    const int tig  = lane & 3;

    const int bx   = blockIdx.x;
    const int wave = bx / 148;
    const int pos  = bx - wave * 148;
    int r;
    if      (wave == 1) r = 295 - pos;
    else if (wave == 3) r = 511 - pos;
    else                r = bx;

    const int qt    = (NQT - 1) - (r >> 4);
    const int sub   = r & 15;
    const int b     = sub & 3;
    const int split = sub >> 2;

    const int nkt = 2 * (qt + 1);
    const int ck  = (nkt + NSPLIT - 1) / NSPLIT;
    const int ks0 = split * ck;
    const int ks1 = min(ks0 + ck, nkt);
    if (ks0 >= ks1) return;

    const int    qb   = qt * QTB;
    const size_t base = (size_t)b * S_;

#pragma unroll
    for (int i = 0; i < 16; i++) {
        int f4 = tid + 128 * i;
        int row = f4 >> 5, c4 = f4 & 31;
        *(float4*)&Qs[row * 128 + ((c4 ^ (row & 7)) << 2)] =
            *(const float4*)&g_q[(base + qb + row) * H_ + c4 * 4];
    }

    float acc[16][4];
#pragma unroll
    for (int nt = 0; nt < 16; nt++)
#pragma unroll
        for (int j = 0; j < 4; j++) acc[nt][j] = 0.0f;

    float mA = -1e30f, mB = -1e30f, lA = 0.0f, lB = 0.0f;
    const int rA   = 16 * w + g;
    const int rowA = qb + rA;
    const int rowB = rowA + 8;

    const float* qrowA = &Qs[rA * 128 + tig];
    const float* qrowB = qrowA + 8 * 128;

    for (int kt = ks0; kt < ks1; kt++) {
        const int kb = kt * KT;

        __syncthreads();
#pragma unroll
        for (int i = 0; i < 8; i++) {
            int f4 = tid + 128 * i;
            int row = f4 >> 5, c4 = f4 & 31;
            *(float4*)&KVs[row * 128 + ((c4 ^ (row & 7)) << 2)] =
                *(const float4*)&g_k[(base + kb + row) * H_ + c4 * 4];
        }
        __syncthreads();

        float s[4][4];
#pragma unroll
        for (int nt = 0; nt < 4; nt++)
#pragma unroll
            for (int j = 0; j < 4; j++) s[nt][j] = 0.0f;

#pragma unroll
        for (int ks = 0; ks < 16; ks++) {
            const int c0 = ((2 * ks)     ^ g) << 2;
            const int c1 = ((2 * ks + 1) ^ g) << 2;
            unsigned aH[4], aL[4];
            split_tf(qrowA[c0], aH[0], aL[0]);
            split_tf(qrowB[c0], aH[1], aL[1]);
            split_tf(qrowA[c1], aH[2], aL[2]);
            split_tf(qrowB[c1], aH[3], aL[3]);
#pragma unroll
            for (int nt = 0; nt < 4; nt++) {
                const float* kr = &KVs[(8 * nt + g) * 128 + tig];
                unsigned bH[2], bL[2];
                split_tf(kr[c0], bH[0], bL[0]);
                split_tf(kr[c1], bH[1], bL[1]);
                MMA_TF32(s[nt], aH, bH);
                MMA_TF32(s[nt], aH, bL);
                MMA_TF32(s[nt], aL, bH);
            }
        }

#pragma unroll
        for (int nt = 0; nt < 4; nt++) {
            int c0 = kb + 8 * nt + 2 * tig;
            int c1 = c0 + 1;
            if (c0 > rowA) s[nt][0] = -1e30f;
            if (c1 > rowA) s[nt][1] = -1e30f;
            if (c0 > rowB) s[nt][2] = -1e30f;
            if (c1 > rowB) s[nt][3] = -1e30f;
        }

        float mxA = -1e30f, mxB = -1e30f;
#pragma unroll
        for (int nt = 0; nt < 4; nt++) {
            mxA = fmaxf(mxA, fmaxf(s[nt][0], s[nt][1]));
            mxB = fmaxf(mxB, fmaxf(s[nt][2], s[nt][3]));
        }
        mxA = fmaxf(mxA, __shfl_xor_sync(0xffffffffu, mxA, 1));
        mxA = fmaxf(mxA, __shfl_xor_sync(0xffffffffu, mxA, 2));
        mxB = fmaxf(mxB, __shfl_xor_sync(0xffffffffu, mxB, 1));
        mxB = fmaxf(mxB, __shfl_xor_sync(0xffffffffu, mxB, 2));

        float mAn = fmaxf(mA, mxA), mBn = fmaxf(mB, mxB);
        float cA = __expf(mA - mAn), cB = __expf(mB - mBn);
        float sumA = 0.0f, sumB = 0.0f;
#pragma unroll
        for (int nt = 0; nt < 4; nt++) {
            s[nt][0] = __expf(s[nt][0] - mAn);
            s[nt][1] = __expf(s[nt][1] - mAn);
            s[nt][2] = __expf(s[nt][2] - mBn);
            s[nt][3] = __expf(s[nt][3] - mBn);
            sumA += s[nt][0] + s[nt][1];
            sumB += s[nt][2] + s[nt][3];
        }
        sumA += __shfl_xor_sync(0xffffffffu, sumA, 1);
        sumA += __shfl_xor_sync(0xffffffffu, sumA, 2);
        sumB += __shfl_xor_sync(0xffffffffu, sumB, 1);
        sumB += __shfl_xor_sync(0xffffffffu, sumB, 2);
        lA = lA * cA + sumA;
        lB = lB * cB + sumB;
        mA = mAn; mB = mBn;
#pragma unroll
        for (int nt = 0; nt < 16; nt++) {
            acc[nt][0] *= cA; acc[nt][1] *= cA;
            acc[nt][2] *= cB; acc[nt][3] *= cB;
        }

        __syncthreads();
#pragma unroll
        for (int i = 0; i < 8; i++) {
            int f4 = tid + 128 * i;
            int row = f4 >> 5, c4 = f4 & 31;
            *(float4*)&KVs[row * 128 + ((c4 ^ (row & 7)) << 2)] =
                *(const float4*)&g_v[(base + kb + row) * H_ + c4 * 4];
        }
        __syncthreads();

        const int srcE = (lane & ~3) | (tig >> 1);
        const int srcO = srcE + 2;
        const int gh   = g >> 2;
        const int gl   = g & 3;
#pragma unroll
        for (int ka = 0; ka < 4; ka++) {
            float e, o, a0f, a1f, a2f, a3f;
            e = __shfl_sync(0xffffffffu, s[ka][0], srcE);
            o = __shfl_sync(0xffffffffu, s[ka][1], srcE);
            a0f = (tig & 1) ? o : e;
            e = __shfl_sync(0xffffffffu, s[ka][0], srcO);
            o = __shfl_sync(0xffffffffu, s[ka][1], srcO);
            a2f = (tig & 1) ? o : e;
            e = __shfl_sync(0xffffffffu, s[ka][2], srcE);
            o = __shfl_sync(0xffffffffu, s[ka][3], srcE);
            a1f = (tig & 1) ? o : e;
            e = __shfl_sync(0xffffffffu, s[ka][2], srcO);
            o = __shfl_sync(0xffffffffu, s[ka][3], srcO);
            a3f = (tig & 1) ? o : e;

            unsigned aH[4], aL[4];
            split_tf(a0f, aH[0], aL[0]);
            split_tf(a1f, aH[1], aL[1]);
            split_tf(a2f, aH[2], aL[2]);
            split_tf(a3f, aH[3], aL[3]);

            const float* v0 = &KVs[(8 * ka + tig) * 128 + gl];
            const float* v1 = &KVs[(8 * ka + tig + 4) * 128 + gl];
#pragma unroll
            for (int nt = 0; nt < 16; nt++) {
                const int o0 = ((2 * nt + gh) ^ tig) << 2;
                const int o1 = o0 ^ 16;
                unsigned bH[2], bL[2];
                split_tf(v0[o0], bH[0], bL[0]);
                split_tf(v1[o1], bH[1], bL[1]);
                MMA_TF32(acc[nt], aH, bH);
                MMA_TF32(acc[nt], aH, bL);
                MMA_TF32(acc[nt], aL, bH);
            }
        }
    }

    const size_t growA = (size_t)split * M_ + base + rowA;
    const size_t growB = growA + 8;
#pragma unroll
    for (int nt = 0; nt < 16; nt++) {
        *(float2*)&g_opart[growA * H_ + 8 * nt + 2 * tig] =
            make_float2(acc[nt][0], acc[nt][1]);
        *(float2*)&g_opart[growB * H_ + 8 * nt + 2 * tig] =
            make_float2(acc[nt][2], acc[nt][3]);
    }
    if (tig == 0) {
        g_mpart[growA] = mA; g_lpart[growA] = lA;
        g_mpart[growB] = mB; g_lpart[growB] = lB;
    }
}

// ---------------------------------------------------------------------------
// Combine kernel: merge NSPLIT partials per row.
// ---------------------------------------------------------------------------
__global__ __launch_bounds__(256) void combine_kernel(float* __restrict__ out)
{
    const int t   = blockIdx.x * 256 + threadIdx.x;
    const int row = t >> 5;
    const int h   = (t & 31) * 4;

    const int qt  = (row & (S_ - 1)) >> 6;            // QTB=64
    const int nkt = 2 * (qt + 1);
    const int ck  = (nkt + NSPLIT - 1) / NSPLIT;

    float ms[NSPLIT];
    float M = -1e30f;
#pragma unroll
    for (int sp = 0; sp < NSPLIT; sp++) {
        bool valid = (sp * ck < nkt);
        ms[sp] = valid ? g_mpart[sp * M_ + row] : -1e30f;
        M = fmaxf(M, ms[sp]);
    }

    float L = 0.0f;
    float4 o = make_float4(0.f, 0.f, 0.f, 0.f);
#pragma unroll
    for (int sp = 0; sp < NSPLIT; sp++) {
        if (sp * ck < nkt) {
            float e = __expf(ms[sp] - M);
            L += e * g_lpart[sp * M_ + row];
            float4 v = *(const float4*)&g_opart[((size_t)sp * M_ + row) * H_ + h];
            o.x += e * v.x; o.y += e * v.y; o.z += e * v.z; o.w += e * v.w;
        }
    }
    float inv = 1.0f / L;
    float4 rr = make_float4(o.x * inv, o.y * inv, o.z * inv, o.w * inv);
    *(float4*)&out[(size_t)row * H_ + h] = rr;
}

// ---------------------------------------------------------------------------
extern "C" void kernel_launch(void* const* d_in, const int* in_sizes, int n_in,
                              void* d_out, int out_size)
{
    const float* x  = (const float*)d_in[0];
    const float* Wq = (const float*)d_in[1];
    const float* Wk = (const float*)d_in[2];
    const float* Wv = (const float*)d_in[3];
    float* out = (float*)d_out;

    dim3 pg(M_ / 64, 3);
    proj_kernel<<<pg, 128>>>(x, Wq, Wk, Wv);
    attn_kernel<<<NSPLIT * B_ * NQT, 128>>>();
    combine_kernel<<<(M_ * H_ / 4) / 256, 256>>>(out);
}